// round 2
// baseline (speedup 1.0000x reference)
#include <cuda_runtime.h>
#include <math.h>

// Shapes (fixed for this problem)
#define NB 4
#define CC 256
#define LL 4096
#define NH 8
#define HD 32

// Scratch (no cudaMalloc allowed): PE table (transposed, matches x layout) + qkv activations
__device__ float g_peT[(size_t)CC * LL];                 // 4 MB
__device__ float g_qkv[(size_t)NB * LL * 768];           // 50 MB

// ---------------------------------------------------------------------------
// Kernel 0: positional encoding, transposed: peT[c][l]
// ---------------------------------------------------------------------------
__global__ void pe_kernel() {
    int idx = blockIdx.x * 256 + threadIdx.x;
    if (idx >= CC * LL) return;
    int c = idx >> 12;          // 0..255
    int l = idx & (LL - 1);     // 0..4095
    double e = (double)((c >> 1) * 2) / 256.0;
    double denom = pow(10000.0, e);
    double ang = (double)l / denom;
    g_peT[idx] = (c & 1) ? (float)cos(ang) : (float)sin(ang);
}

// ---------------------------------------------------------------------------
// Kernel 1: qkv = (x^T + PE) @ W_qkv     M=16384, K=256, N=768
// Block tile 128x64, 256 threads, 8x4 micro-tile, K-chunks of 32.
// A element [m][k] = x[n][k][l] + peT[k][l]  (n=m>>12, l=m&4095): coalesced in l.
// ---------------------------------------------------------------------------
__global__ __launch_bounds__(256) void qkv_gemm(const float* __restrict__ x,
                                                const float* __restrict__ W) {
    __shared__ float AsT[32][128];   // [k][m-local]
    __shared__ float Bs[32][64];     // [k][j-local]

    const int m0 = blockIdx.x * 128;
    const int j0 = blockIdx.y * 64;
    const int n  = m0 >> 12;
    const int l0 = m0 & (LL - 1);
    const int tid = threadIdx.x;
    const int tx = tid & 15;         // col group (x4)
    const int ty = tid >> 4;         // row group (x8)

    float acc[8][4];
#pragma unroll
    for (int i = 0; i < 8; i++)
#pragma unroll
        for (int j = 0; j < 4; j++) acc[i][j] = 0.0f;

    const float* xb = x + (size_t)n * CC * LL;

    for (int c0 = 0; c0 < 256; c0 += 32) {
        __syncthreads();
        // A tile: 128 rows(l) x 32 cols(c) -> AsT[c][l], 1024 float4 loads
#pragma unroll
        for (int rep = 0; rep < 4; rep++) {
            int e = tid + rep * 256;
            int c = e >> 5;
            int lq = (e & 31) * 4;
            const float4 xv = *(const float4*)(xb + (size_t)(c0 + c) * LL + l0 + lq);
            const float4 pv = *(const float4*)(g_peT + (size_t)(c0 + c) * LL + l0 + lq);
            *(float4*)&AsT[c][lq] = make_float4(xv.x + pv.x, xv.y + pv.y,
                                                xv.z + pv.z, xv.w + pv.w);
        }
        // B tile: 32 x 64
#pragma unroll
        for (int rep = 0; rep < 2; rep++) {
            int e = tid + rep * 256;
            int c = e >> 4;
            int j4 = (e & 15) * 4;
            *(float4*)&Bs[c][j4] = *(const float4*)(W + (size_t)(c0 + c) * 768 + j0 + j4);
        }
        __syncthreads();

#pragma unroll
        for (int kk = 0; kk < 32; kk++) {
            float4 a0 = *(float4*)&AsT[kk][ty * 8];
            float4 a1 = *(float4*)&AsT[kk][ty * 8 + 4];
            float4 b  = *(float4*)&Bs[kk][tx * 4];
            float a[8] = {a0.x, a0.y, a0.z, a0.w, a1.x, a1.y, a1.z, a1.w};
            float bb[4] = {b.x, b.y, b.z, b.w};
#pragma unroll
            for (int i = 0; i < 8; i++)
#pragma unroll
                for (int j = 0; j < 4; j++) acc[i][j] += a[i] * bb[j];
        }
    }

#pragma unroll
    for (int i = 0; i < 8; i++) {
        size_t m = (size_t)m0 + ty * 8 + i;
        *(float4*)(g_qkv + m * 768 + j0 + tx * 4) =
            make_float4(acc[i][0], acc[i][1], acc[i][2], acc[i][3]);
    }
}

// ---------------------------------------------------------------------------
// Kernel 2: fp32 flash attention. grid = (qtile=64, h=8, n=4), 256 threads.
// BQ=BK=64, d=32. Online softmax, S tile staged in smem.
// ---------------------------------------------------------------------------
__global__ __launch_bounds__(256) void attn_kernel(float* __restrict__ out) {
    __shared__ float qsT[32][68];    // [d][q-row], pre-scaled
    __shared__ float ksT[32][68];    // [d][k-row]
    __shared__ float vs[64][32];     // [k-row][d]
    __shared__ float S[64][68];      // scores / probs

    const int qt = blockIdx.x, h = blockIdx.y, n = blockIdx.z;
    const int tid = threadIdx.x;
    const float* base = g_qkv + (size_t)n * LL * 768;
    const float* Qp = base + h * HD;           // q at cols [0,256)
    const float* Kp = base + 256 + h * HD;     // k at cols [256,512)
    const float* Vp = base + 512 + h * HD;     // v at cols [512,768)
    const int l0 = qt * 64;
    const float scale = 0.17677669529663688f;  // 1/sqrt(32)

    // Load + scale Q tile (64 x 32) -> qsT[d][r]
#pragma unroll
    for (int rep = 0; rep < 2; rep++) {
        int f = tid + rep * 256;
        int r = f >> 3;
        int d4 = (f & 7) * 4;
        float4 v = *(const float4*)(Qp + (size_t)(l0 + r) * 768 + d4);
        qsT[d4 + 0][r] = v.x * scale;
        qsT[d4 + 1][r] = v.y * scale;
        qsT[d4 + 2][r] = v.z * scale;
        qsT[d4 + 3][r] = v.w * scale;
    }

    // S-compute view: 16x16 threads, 4x4 micro
    const int ty = tid >> 4, tx = tid & 15;
    // row view: 4 threads per row, 8 d-cols each
    const int rr = tid >> 2, quad = tid & 3, dd = quad * 8;

    float o[8];
#pragma unroll
    for (int j = 0; j < 8; j++) o[j] = 0.0f;
    float m_i = -1e30f, l_i = 0.0f;

    for (int kt = 0; kt < 64; kt++) {
        __syncthreads();   // protect ksT/vs/S from previous-iter readers (and Q load @ kt=0)
        const int c0 = kt * 64;
#pragma unroll
        for (int rep = 0; rep < 2; rep++) {
            int f = tid + rep * 256;
            int c = f >> 3;
            int d4 = (f & 7) * 4;
            float4 kv4 = *(const float4*)(Kp + (size_t)(c0 + c) * 768 + d4);
            ksT[d4 + 0][c] = kv4.x;
            ksT[d4 + 1][c] = kv4.y;
            ksT[d4 + 2][c] = kv4.z;
            ksT[d4 + 3][c] = kv4.w;
            *(float4*)&vs[c][d4] = *(const float4*)(Vp + (size_t)(c0 + c) * 768 + d4);
        }
        __syncthreads();

        // S = Q K^T (scaled)
        float acc[4][4];
#pragma unroll
        for (int i = 0; i < 4; i++)
#pragma unroll
            for (int j = 0; j < 4; j++) acc[i][j] = 0.0f;
#pragma unroll
        for (int k = 0; k < 32; k++) {
            float4 qa = *(float4*)&qsT[k][ty * 4];
            float4 kb = *(float4*)&ksT[k][tx * 4];
            float a[4] = {qa.x, qa.y, qa.z, qa.w};
            float b[4] = {kb.x, kb.y, kb.z, kb.w};
#pragma unroll
            for (int i = 0; i < 4; i++)
#pragma unroll
                for (int j = 0; j < 4; j++) acc[i][j] += a[i] * b[j];
        }
#pragma unroll
        for (int i = 0; i < 4; i++)
            *(float4*)&S[ty * 4 + i][tx * 4] =
                make_float4(acc[i][0], acc[i][1], acc[i][2], acc[i][3]);
        __syncthreads();

        // Online softmax, row-view
        float vals[16];
        float mx = -1e30f;
#pragma unroll
        for (int i4 = 0; i4 < 4; i4++) {
            float4 sv = *(float4*)&S[rr][quad * 16 + i4 * 4];
            vals[i4 * 4 + 0] = sv.x; vals[i4 * 4 + 1] = sv.y;
            vals[i4 * 4 + 2] = sv.z; vals[i4 * 4 + 3] = sv.w;
            mx = fmaxf(mx, fmaxf(fmaxf(sv.x, sv.y), fmaxf(sv.z, sv.w)));
        }
        mx = fmaxf(mx, __shfl_xor_sync(0xffffffffu, mx, 1));
        mx = fmaxf(mx, __shfl_xor_sync(0xffffffffu, mx, 2));
        float new_m = fmaxf(m_i, mx);
        float factor = __expf(m_i - new_m);
        float psum = 0.0f;
#pragma unroll
        for (int i = 0; i < 16; i++) {
            float p = __expf(vals[i] - new_m);
            vals[i] = p;
            psum += p;
        }
#pragma unroll
        for (int i4 = 0; i4 < 4; i4++)
            *(float4*)&S[rr][quad * 16 + i4 * 4] =
                make_float4(vals[i4 * 4], vals[i4 * 4 + 1], vals[i4 * 4 + 2], vals[i4 * 4 + 3]);
        psum += __shfl_xor_sync(0xffffffffu, psum, 1);
        psum += __shfl_xor_sync(0xffffffffu, psum, 2);
        l_i = l_i * factor + psum;
        m_i = new_m;
#pragma unroll
        for (int j = 0; j < 8; j++) o[j] *= factor;
        __syncwarp();   // P writes by the 4 quad lanes of each row are warp-local

        // O += P V
#pragma unroll 4
        for (int c = 0; c < 64; c++) {
            float p = S[rr][c];
            float4 v0 = *(float4*)&vs[c][dd];
            float4 v1 = *(float4*)&vs[c][dd + 4];
            o[0] += p * v0.x; o[1] += p * v0.y; o[2] += p * v0.z; o[3] += p * v0.w;
            o[4] += p * v1.x; o[5] += p * v1.y; o[6] += p * v1.z; o[7] += p * v1.w;
        }
    }

    // Epilogue: normalize, write to (N, C, H*W) layout
    const float inv = 1.0f / l_i;
    const int l = l0 + rr;
    float* op = out + ((size_t)(n * CC + h * HD + dd)) * LL + l;
#pragma unroll
    for (int j = 0; j < 8; j++) op[(size_t)j * LL] = o[j] * inv;
}

// ---------------------------------------------------------------------------
extern "C" void kernel_launch(void* const* d_in, const int* in_sizes, int n_in,
                              void* d_out, int out_size) {
    const float* x = (const float*)d_in[0];   // (4,256,64,64) fp32
    const float* W = (const float*)d_in[1];   // (256,768) fp32
    float* out = (float*)d_out;               // (4,256,64,64) fp32

    pe_kernel<<<(CC * LL + 255) / 256, 256>>>();
    qkv_gemm<<<dim3(128, 12), 256>>>(x, W);
    attn_kernel<<<dim3(64, NH, NB), 256>>>(out);
}

// round 8
// speedup vs baseline: 4.6120x; 4.6120x over previous
#include <cuda_runtime.h>
#include <math.h>
#include <stdint.h>

#define NB 4
#define CC 256
#define LL 4096
#define NH 8
#define HD 32

__device__ float g_peT[(size_t)CC * LL];                 // 4 MB
__device__ float g_qkv[(size_t)NB * LL * 768];           // 50 MB

// ============================ helpers ============================
__device__ __forceinline__ uint32_t f2tf32(float f) {
    uint32_t r;
    asm("cvt.rna.tf32.f32 %0, %1;" : "=r"(r) : "f"(f));
    return r;
}

// D += A(16x8) * B(8x8)^T-ish: m16n8k8 tf32, fp32 accum (baseline HMMA, no tcgen05)
__device__ __forceinline__ void mma_tf32(float c[4], const uint32_t a[4],
                                         const uint32_t b0, const uint32_t b1) {
    asm volatile(
        "mma.sync.aligned.m16n8k8.row.col.f32.tf32.tf32.f32 "
        "{%0,%1,%2,%3}, {%4,%5,%6,%7}, {%8,%9}, {%0,%1,%2,%3};"
        : "+f"(c[0]), "+f"(c[1]), "+f"(c[2]), "+f"(c[3])
        : "r"(a[0]), "r"(a[1]), "r"(a[2]), "r"(a[3]), "r"(b0), "r"(b1));
}

// ---------------------------------------------------------------------------
// Kernel 0: positional encoding, transposed: peT[c][l].
// ---------------------------------------------------------------------------
__global__ void pe_kernel() {
    __shared__ double s_inv;
    const int c = blockIdx.y;
    if (threadIdx.x == 0) {
        double e = (double)((c >> 1) * 2) / 256.0;
        s_inv = pow(10000.0, -e);
    }
    __syncthreads();
    const int l = blockIdx.x * 256 + threadIdx.x;
    double ang = (double)l * s_inv;
    const double TWO_PI = 6.283185307179586476925286766559;
    double k = floor(ang / TWO_PI);
    float r = (float)(ang - k * TWO_PI);
    g_peT[(size_t)c * LL + l] = (c & 1) ? cosf(r) : sinf(r);
}

// ---------------------------------------------------------------------------
// Kernel 1: qkv = (x^T + PE) @ W_qkv   M=16384, K=256, N=768, tf32 mma.sync
// Block 256 thr (8 warps), tile 128(m) x 64(n); warp w owns rows [16w,16w+16).
// ---------------------------------------------------------------------------
#define PA 136   /* AsT row pad (words): bank = 8t+g, conflict-free a-frag LDS */
#define PB 72    /* Bs row pad: bank = 8t+g, conflict-free b-frag LDS */

__global__ __launch_bounds__(256) void qkv_mma(const float* __restrict__ x,
                                               const float* __restrict__ W) {
    __shared__ uint32_t AsT[32 * PA];   // [k-local][m]
    __shared__ uint32_t Bs[32 * PB];    // [k-local][n]

    const int m0 = blockIdx.x * 128, j0 = blockIdx.y * 64;
    const int n  = m0 >> 12;
    const int l0 = m0 & (LL - 1);
    const int tid = threadIdx.x, w = tid >> 5, lane = tid & 31;
    const int g = lane >> 2, t = lane & 3;
    const float* xb = x + (size_t)n * CC * LL;

    float Cv[8][4];
#pragma unroll
    for (int nb = 0; nb < 8; nb++)
#pragma unroll
        for (int i = 0; i < 4; i++) Cv[nb][i] = 0.0f;

    const int ac = tid >> 3, alq = (tid & 7) * 16;   // A staging: 16 floats along l
    const int bk = tid >> 3, bj8 = (tid & 7) * 8;    // B staging: 8 floats along n

    for (int kc = 0; kc < 256; kc += 32) {
        __syncthreads();
        {
            const float* xr = xb + (size_t)(kc + ac) * LL + l0 + alq;
            const float* pr = g_peT + (size_t)(kc + ac) * LL + l0 + alq;
            uint32_t* ar = AsT + ac * PA + alq;
#pragma unroll
            for (int j = 0; j < 4; j++) {
                float4 xv = *(const float4*)(xr + 4 * j);
                float4 pv = *(const float4*)(pr + 4 * j);
                uint4 o;
                o.x = f2tf32(xv.x + pv.x); o.y = f2tf32(xv.y + pv.y);
                o.z = f2tf32(xv.z + pv.z); o.w = f2tf32(xv.w + pv.w);
                *(uint4*)(ar + 4 * j) = o;
            }
            const float* wr = W + (size_t)(kc + bk) * 768 + j0 + bj8;
            uint32_t* br = Bs + bk * PB + bj8;
#pragma unroll
            for (int j = 0; j < 2; j++) {
                float4 wv = *(const float4*)(wr + 4 * j);
                uint4 o;
                o.x = f2tf32(wv.x); o.y = f2tf32(wv.y);
                o.z = f2tf32(wv.z); o.w = f2tf32(wv.w);
                *(uint4*)(br + 4 * j) = o;
            }
        }
        __syncthreads();

        const int wr0 = w * 16;
#pragma unroll
        for (int s = 0; s < 4; s++) {
            uint32_t a[4];
            a[0] = AsT[(s * 8 + t) * PA + wr0 + g];
            a[1] = AsT[(s * 8 + t) * PA + wr0 + g + 8];
            a[2] = AsT[(s * 8 + t + 4) * PA + wr0 + g];
            a[3] = AsT[(s * 8 + t + 4) * PA + wr0 + g + 8];
#pragma unroll
            for (int nbk = 0; nbk < 8; nbk++) {
                uint32_t b0 = Bs[(s * 8 + t) * PB + nbk * 8 + g];
                uint32_t b1 = Bs[(s * 8 + t + 4) * PB + nbk * 8 + g];
                mma_tf32(Cv[nbk], a, b0, b1);
            }
        }
    }

#pragma unroll
    for (int nbk = 0; nbk < 8; nbk++) {
        size_t row = (size_t)m0 + w * 16 + g;
        int col = j0 + nbk * 8 + 2 * t;
        *(float2*)(g_qkv + row * 768 + col) = make_float2(Cv[nbk][0], Cv[nbk][1]);
        *(float2*)(g_qkv + (row + 8) * 768 + col) = make_float2(Cv[nbk][2], Cv[nbk][3]);
    }
}

// ---------------------------------------------------------------------------
// Kernel 2: tf32 mma.sync flash attention, no-max softmax, O in registers.
// grid(32 qtiles, 8 h, 4 n), 256 thr (8 warps); warp owns 16 q-rows; BK=64.
// ---------------------------------------------------------------------------
#define PK 36   /* Ks pad: b-frag bank = 4g+t, conflict-free */
#define PV 40   /* Vs pad: b-frag bank = 8t+g, conflict-free */

__global__ __launch_bounds__(256) void attn_mma(float* __restrict__ out) {
    __shared__ uint32_t Ks[64 * PK];   // [kv][d] tf32
    __shared__ uint32_t Vs[64 * PV];   // [kv][d] tf32

    const int qt = blockIdx.x, h = blockIdx.y, n = blockIdx.z;
    const int tid = threadIdx.x, w = tid >> 5, lane = tid & 31;
    const int g = lane >> 2, t = lane & 3;
    const float* bptr = g_qkv + (size_t)n * LL * 768;
    const float* Qp = bptr + h * HD;
    const float* Kp = bptr + 256 + h * HD;
    const float* Vp = bptr + 512 + h * HD;
    const int l0 = qt * 128;
    const float scale = 0.17677669529663688f;   // 1/sqrt(32)

    // Q fragments held in registers for the whole CTA lifetime (one-time LDG)
    uint32_t qa[4][4];
    {
        const int r0 = l0 + w * 16 + g, r1 = r0 + 8;
#pragma unroll
        for (int s = 0; s < 4; s++) {
            qa[s][0] = f2tf32(__ldg(Qp + (size_t)r0 * 768 + s * 8 + t) * scale);
            qa[s][1] = f2tf32(__ldg(Qp + (size_t)r1 * 768 + s * 8 + t) * scale);
            qa[s][2] = f2tf32(__ldg(Qp + (size_t)r0 * 768 + s * 8 + t + 4) * scale);
            qa[s][3] = f2tf32(__ldg(Qp + (size_t)r1 * 768 + s * 8 + t + 4) * scale);
        }
    }

    float O[4][4];
#pragma unroll
    for (int nb2 = 0; nb2 < 4; nb2++)
#pragma unroll
        for (int i = 0; i < 4; i++) O[nb2][i] = 0.0f;
    float lsum0 = 0.0f, lsum1 = 0.0f;   // row g / row g+8 partial softmax sums

    const int sr = tid >> 2, sd = (tid & 3) * 8;   // staging: row, d-offset
    const int base4 = lane & ~3;                   // lane group base for shfl
    const int srcA = base4 + (t >> 1);
    const int srcB = base4 + 2 + (t >> 1);
    const bool odd = (t & 1);

    for (int kt = 0; kt < 64; kt++) {
        const int c0 = kt * 64;
        __syncthreads();
        // Stage K, V tiles (64 x 32) as tf32
        {
            const float* kr = Kp + (size_t)(c0 + sr) * 768 + sd;
            const float* vr = Vp + (size_t)(c0 + sr) * 768 + sd;
            float4 k0 = *(const float4*)(kr), k1 = *(const float4*)(kr + 4);
            float4 v0 = *(const float4*)(vr), v1 = *(const float4*)(vr + 4);
            uint32_t* kw = Ks + sr * PK + sd;
            uint32_t* vw = Vs + sr * PV + sd;
            *(uint2*)(kw + 0) = make_uint2(f2tf32(k0.x), f2tf32(k0.y));
            *(uint2*)(kw + 2) = make_uint2(f2tf32(k0.z), f2tf32(k0.w));
            *(uint2*)(kw + 4) = make_uint2(f2tf32(k1.x), f2tf32(k1.y));
            *(uint2*)(kw + 6) = make_uint2(f2tf32(k1.z), f2tf32(k1.w));
            *(uint2*)(vw + 0) = make_uint2(f2tf32(v0.x), f2tf32(v0.y));
            *(uint2*)(vw + 2) = make_uint2(f2tf32(v0.z), f2tf32(v0.w));
            *(uint2*)(vw + 4) = make_uint2(f2tf32(v1.x), f2tf32(v1.y));
            *(uint2*)(vw + 6) = make_uint2(f2tf32(v1.z), f2tf32(v1.w));
        }
        __syncthreads();

        // S = Q K^T : 8 n-blocks of 8 kv, k-dim = d (4 steps of 8)
        float Cv[8][4];
#pragma unroll
        for (int nbk = 0; nbk < 8; nbk++)
#pragma unroll
            for (int i = 0; i < 4; i++) Cv[nbk][i] = 0.0f;
#pragma unroll
        for (int s = 0; s < 4; s++) {
#pragma unroll
            for (int nbk = 0; nbk < 8; nbk++) {
                uint32_t b0 = Ks[(nbk * 8 + g) * PK + s * 8 + t];
                uint32_t b1 = Ks[(nbk * 8 + g) * PK + s * 8 + t + 4];
                mma_tf32(Cv[nbk], qa[s], b0, b1);
            }
        }

        // Softmax without max-subtraction; P kept in registers (tf32 patterns).
        uint32_t P[8][4];
#pragma unroll
        for (int nbk = 0; nbk < 8; nbk++) {
            uint32_t p0 = f2tf32(__expf(Cv[nbk][0]));
            uint32_t p1 = f2tf32(__expf(Cv[nbk][1]));
            uint32_t p2 = f2tf32(__expf(Cv[nbk][2]));
            uint32_t p3 = f2tf32(__expf(Cv[nbk][3]));
            // sum the tf32-rounded values so numerator/denominator match
            lsum0 += __uint_as_float(p0) + __uint_as_float(p1);
            lsum1 += __uint_as_float(p2) + __uint_as_float(p3);
            P[nbk][0] = p0; P[nbk][1] = p1; P[nbk][2] = p2; P[nbk][3] = p3;
        }

        // O += P V : k-dim = kv (8 steps of 8, each = one n-block of S)
#pragma unroll
        for (int s = 0; s < 8; s++) {
            // C-fragment -> A-fragment permutation via shfl (cols {2t,2t+1} -> {t,t+4})
            uint32_t a[4];
            uint32_t u0 = __shfl_sync(0xffffffffu, P[s][0], srcA);
            uint32_t u1 = __shfl_sync(0xffffffffu, P[s][1], srcA);
            a[0] = odd ? u1 : u0;
            uint32_t w0 = __shfl_sync(0xffffffffu, P[s][0], srcB);
            uint32_t w1 = __shfl_sync(0xffffffffu, P[s][1], srcB);
            a[2] = odd ? w1 : w0;
            uint32_t x0 = __shfl_sync(0xffffffffu, P[s][2], srcA);
            uint32_t x1 = __shfl_sync(0xffffffffu, P[s][3], srcA);
            a[1] = odd ? x1 : x0;
            uint32_t y0 = __shfl_sync(0xffffffffu, P[s][2], srcB);
            uint32_t y1 = __shfl_sync(0xffffffffu, P[s][3], srcB);
            a[3] = odd ? y1 : y0;
#pragma unroll
            for (int nb2 = 0; nb2 < 4; nb2++) {
                uint32_t b0 = Vs[(s * 8 + t) * PV + nb2 * 8 + g];
                uint32_t b1 = Vs[(s * 8 + t + 4) * PV + nb2 * 8 + g];
                mma_tf32(O[nb2], a, b0, b1);
            }
        }
    }

    // Row-sum reduction across the 4 lanes of each row group
    lsum0 += __shfl_xor_sync(0xffffffffu, lsum0, 1);
    lsum0 += __shfl_xor_sync(0xffffffffu, lsum0, 2);
    lsum1 += __shfl_xor_sync(0xffffffffu, lsum1, 1);
    lsum1 += __shfl_xor_sync(0xffffffffu, lsum1, 2);
    const float inv0 = 1.0f / lsum0, inv1 = 1.0f / lsum1;

    // Epilogue: out[(n*C + h*32 + d) * L + q]
    const int q0 = l0 + w * 16 + g;
    float* ob = out + ((size_t)(n * CC + h * HD)) * LL;
#pragma unroll
    for (int nb2 = 0; nb2 < 4; nb2++) {
        int d = nb2 * 8 + 2 * t;
        ob[(size_t)d * LL + q0]           = O[nb2][0] * inv0;
        ob[(size_t)(d + 1) * LL + q0]     = O[nb2][1] * inv0;
        ob[(size_t)d * LL + q0 + 8]       = O[nb2][2] * inv1;
        ob[(size_t)(d + 1) * LL + q0 + 8] = O[nb2][3] * inv1;
    }
}

// ---------------------------------------------------------------------------
extern "C" void kernel_launch(void* const* d_in, const int* in_sizes, int n_in,
                              void* d_out, int out_size) {
    const float* x = (const float*)d_in[0];   // (4,256,64,64) fp32
    const float* W = (const float*)d_in[1];   // (256,768) fp32
    float* out = (float*)d_out;               // (4,256,64,64) fp32

    pe_kernel<<<dim3(16, 256), 256>>>();
    qkv_mma<<<dim3(128, 12), 256>>>(x, W);
    attn_mma<<<dim3(32, NH, NB), 256>>>(out);
}